// round 4
// baseline (speedup 1.0000x reference)
#include <cuda_runtime.h>
#include <cuda_bf16.h>

// MaxBlurPooling1D: x (16, 8192, 256) f32 -> z (16, 4096, 256) f32
// z[b,j,c] = w0*m[2j-1] + w1*m[2j] + w2*m[2j+1] + w3*m[2j+2]
//   m[l] = max(x[l], x[l+1]) for l<=L-2 ; m[L-1] = x[L-1] ; m[-1] = m[L] = 0
//
// Round-3 changes vs round 2:
//  - Residency is the binding constraint (R2 post-mortem): 128-thread blocks,
//    __launch_bounds__(128, 12) -> 12 blocks/SM = 1536 threads/SM (75% occ),
//    +50% outstanding loads vs R1's 1024 threads/SM.
//  - grid = 2048 blocks (1.15 waves, short blocks -> cheap tail)
//  - JPT stays 16 (read amp 1.094x), inner unroll 8 (keeps regs ~39 <= 42 cap)

#define L_DIM  8192
#define C4     64      // 256 f32 channels = 64 float4 lanes
#define J_OUT  4096
#define JPT    16      // outputs per thread along L
#define BY     2       // thread.y chunks per block

__device__ __forceinline__ float4 f4max(float4 a, float4 b) {
    return make_float4(fmaxf(a.x, b.x), fmaxf(a.y, b.y),
                       fmaxf(a.z, b.z), fmaxf(a.w, b.w));
}

__global__ void __launch_bounds__(128, 12)
mbp1d_kernel(const float4* __restrict__ x,
             const float*  __restrict__ blur,
             const float*  __restrict__ avg,
             float4* __restrict__ z)
{
    // Fold blur (b0,b1,b2) and avg (a0,a1) into 4 taps over m[]
    const float b0 = blur[0], b1 = blur[1], b2 = blur[2];
    const float a0 = avg[0],  a1 = avg[1];
    const float w0 = a0 * b0;
    const float w1 = a0 * b1 + a1 * b0;
    const float w2 = a0 * b2 + a1 * b1;
    const float w3 = a1 * b2;

    const int c  = threadIdx.x;                                   // 0..63 float4 lane
    const int b  = blockIdx.y;                                    // batch
    const int j0 = (blockIdx.x * BY + threadIdx.y) * JPT;         // first output row

    const float4* xb = x + (size_t)b * L_DIM * C4 + c;
    float4*       zb = z + ((size_t)b * J_OUT + j0) * C4 + c;

    const float4 zero = make_float4(0.f, 0.f, 0.f, 0.f);

    // Rolling state at loop top for iteration j:
    //   mA = m[2j-1], mB = m[2j], xlast = x[2j+1]
    float4 mA, mB, xlast;
    {
        const float4 x0 = __ldcs(&xb[(size_t)(2 * j0) * C4]);
        const float4 x1 = __ldcs(&xb[(size_t)(2 * j0 + 1) * C4]);
        if (j0 == 0) {
            mA = zero;                                            // m[-1] = 0 (pad)
        } else {
            const float4 xm1 = __ldcs(&xb[(size_t)(2 * j0 - 1) * C4]);
            mA = f4max(xm1, x0);
        }
        mB = f4max(x0, x1);
        xlast = x1;
    }

    #pragma unroll 8
    for (int t = 0; t < JPT; ++t) {
        const int j  = j0 + t;
        const int r2 = 2 * j + 2;                                 // next even row
        float4 mC, mD;
        if (r2 < L_DIM) {
            const float4 x2 = __ldcs(&xb[(size_t)r2 * C4]);
            const float4 x3 = __ldcs(&xb[(size_t)(r2 + 1) * C4]); // r2 even => r2+1 <= 8191
            mC = f4max(xlast, x2);                                // m[2j+1]
            mD = f4max(x2, x3);                                   // m[2j+2]
            xlast = x3;
        } else {
            // j = 4095: m[8191] = x[8191] (pad is NEG_INF), m[8192] = 0 (zero pad)
            mC = xlast;
            mD = zero;
        }

        float4 o;
        o.x = w0 * mA.x + w1 * mB.x + w2 * mC.x + w3 * mD.x;
        o.y = w0 * mA.y + w1 * mB.y + w2 * mC.y + w3 * mD.y;
        o.z = w0 * mA.z + w1 * mB.z + w2 * mC.z + w3 * mD.z;
        o.w = w0 * mA.w + w1 * mB.w + w2 * mC.w + w3 * mD.w;
        __stcs(&zb[(size_t)t * C4], o);

        mA = mC;
        mB = mD;
    }
}

extern "C" void kernel_launch(void* const* d_in, const int* in_sizes, int n_in,
                              void* d_out, int out_size)
{
    const float4* x    = (const float4*)d_in[0];   // (16, 8192, 256) f32
    const float*  blur = (const float*)d_in[1];    // (3,1,1)
    const float*  avg  = (const float*)d_in[2];    // (2,1,1)
    float4*       z    = (float4*)d_out;           // (16, 4096, 256) f32

    (void)in_sizes; (void)n_in; (void)out_size;

    dim3 block(C4, BY);                            // (64, 2) = 128 threads
    dim3 grid(J_OUT / (BY * JPT), 16);             // (128, 16) = 2048 blocks
    mbp1d_kernel<<<grid, block>>>(x, blur, avg, z);
}

// round 5
// speedup vs baseline: 1.1124x; 1.1124x over previous
#include <cuda_runtime.h>
#include <cuda_bf16.h>

// MaxBlurPooling1D: x (16, 8192, 256) f32 -> z (16, 4096, 256) f32
// z[b,j,c] = w0*m[2j-1] + w1*m[2j] + w2*m[2j+1] + w3*m[2j+2]
//   m[l] = max(x[l], x[l+1]) for l<=L-2 ; m[L-1] = x[L-1] ; m[-1] = m[L] = 0
//
// Round-4: REVERT the two R2/R3 regressions (proven by R3's occupancy
// experiment: +50% resident threads, DRAM unchanged at 61% -> limiter is
// per-warp MLP + cache policy, not residency):
//  - no __ldcs/__stcs (default policy restores L2 halo capture)
//  - FULL unroll (restores ptxas front-batched loads, ~54 regs, high MLP)
// One change vs R1: 128-thread blocks (grid 2048) -> finer tail drain,
// same-or-better residency (9 blocks/SM = 1152 thr/SM).

#define L_DIM  8192
#define C4     64      // 256 f32 channels = 64 float4 lanes
#define J_OUT  4096
#define JPT    16      // outputs per thread along L
#define BY     2       // thread.y chunks per block

__device__ __forceinline__ float4 f4max(float4 a, float4 b) {
    return make_float4(fmaxf(a.x, b.x), fmaxf(a.y, b.y),
                       fmaxf(a.z, b.z), fmaxf(a.w, b.w));
}

__global__ void __launch_bounds__(128)
mbp1d_kernel(const float4* __restrict__ x,
             const float*  __restrict__ blur,
             const float*  __restrict__ avg,
             float4* __restrict__ z)
{
    // Fold blur (b0,b1,b2) and avg (a0,a1) into 4 taps over m[]
    const float b0 = blur[0], b1 = blur[1], b2 = blur[2];
    const float a0 = avg[0],  a1 = avg[1];
    const float w0 = a0 * b0;
    const float w1 = a0 * b1 + a1 * b0;
    const float w2 = a0 * b2 + a1 * b1;
    const float w3 = a1 * b2;

    const int c  = threadIdx.x;                                   // 0..63 float4 lane
    const int b  = blockIdx.y;                                    // batch
    const int j0 = (blockIdx.x * BY + threadIdx.y) * JPT;         // first output row

    const float4* xb = x + (size_t)b * L_DIM * C4 + c;
    float4*       zb = z + ((size_t)b * J_OUT + j0) * C4 + c;

    const float4 zero = make_float4(0.f, 0.f, 0.f, 0.f);

    // Rolling state at loop top for iteration j:
    //   mA = m[2j-1], mB = m[2j], xlast = x[2j+1]
    float4 mA, mB, xlast;
    {
        const float4 x0 = xb[(size_t)(2 * j0) * C4];
        const float4 x1 = xb[(size_t)(2 * j0 + 1) * C4];
        if (j0 == 0) {
            mA = zero;                                            // m[-1] = 0 (pad)
        } else {
            const float4 xm1 = xb[(size_t)(2 * j0 - 1) * C4];
            mA = f4max(xm1, x0);
        }
        mB = f4max(x0, x1);
        xlast = x1;
    }

    #pragma unroll
    for (int t = 0; t < JPT; ++t) {
        const int j  = j0 + t;
        const int r2 = 2 * j + 2;                                 // next even row
        float4 mC, mD;
        if (r2 < L_DIM) {
            const float4 x2 = xb[(size_t)r2 * C4];
            const float4 x3 = xb[(size_t)(r2 + 1) * C4];          // r2 even => r2+1 <= 8191
            mC = f4max(xlast, x2);                                // m[2j+1]
            mD = f4max(x2, x3);                                   // m[2j+2]
            xlast = x3;
        } else {
            // j = 4095: m[8191] = x[8191] (pad is NEG_INF), m[8192] = 0 (zero pad)
            mC = xlast;
            mD = zero;
        }

        float4 o;
        o.x = w0 * mA.x + w1 * mB.x + w2 * mC.x + w3 * mD.x;
        o.y = w0 * mA.y + w1 * mB.y + w2 * mC.y + w3 * mD.y;
        o.z = w0 * mA.z + w1 * mB.z + w2 * mC.z + w3 * mD.z;
        o.w = w0 * mA.w + w1 * mB.w + w2 * mC.w + w3 * mD.w;
        zb[(size_t)t * C4] = o;

        mA = mC;
        mB = mD;
    }
}

extern "C" void kernel_launch(void* const* d_in, const int* in_sizes, int n_in,
                              void* d_out, int out_size)
{
    const float4* x    = (const float4*)d_in[0];   // (16, 8192, 256) f32
    const float*  blur = (const float*)d_in[1];    // (3,1,1)
    const float*  avg  = (const float*)d_in[2];    // (2,1,1)
    float4*       z    = (float4*)d_out;           // (16, 4096, 256) f32

    (void)in_sizes; (void)n_in; (void)out_size;

    dim3 block(C4, BY);                            // (64, 2) = 128 threads
    dim3 grid(J_OUT / (BY * JPT), 16);             // (128, 16) = 2048 blocks
    mbp1d_kernel<<<grid, block>>>(x, blur, avg, z);
}